// round 16
// baseline (speedup 1.0000x reference)
#include <cuda_runtime.h>
#include <cuda_bf16.h>
#include <math.h>

#define KTAP 5
#define N0 78400
#define E0 627200
#define N1 19600
#define E1 156800
#define NP2 4900
#define BATCH 100

// ---------------- scratch (static device globals; no allocation) ----------------
__device__ float d_S1[N0 * 25];        // per-dst tap scalar sums (layer 1)
__device__ float d_deg1[N0];
__device__ float d_p1[N1 * 32];
__device__ __nv_bfloat16 d_y2[N1 * 1600];   // y2[n, tap(25), ch(64)] bf16 (62MB, L2-resident)
__device__ float d_agg2[N1 * 64];
__device__ float d_deg2[N1];
__device__ float d_h2[N1 * 64];
__device__ float d_pool2[NP2 * 64];    // == [100, 3136] for fc1
__device__ float d_f1acc[BATCH * 512];

__device__ __forceinline__ float elu1(float v) { return v > 0.f ? v : expm1f(v); }

__device__ __forceinline__ void red4(float* p, float4 v) {
    asm volatile("red.global.add.v4.f32 [%0], {%1,%2,%3,%4};"
                 :: "l"(p), "f"(v.x), "f"(v.y), "f"(v.z), "f"(v.w) : "memory");
}

// ---- packed fp32x2 helpers ----
__device__ __forceinline__ unsigned long long pack2dup(float a) {
    unsigned long long r;
    asm("mov.b64 %0, {%1,%1};" : "=l"(r) : "f"(a));
    return r;
}
__device__ __forceinline__ void unpack2(unsigned long long v, float& lo, float& hi) {
    asm("mov.b64 {%0,%1}, %2;" : "=f"(lo), "=f"(hi) : "l"(v));
}
__device__ __forceinline__ void fma2(unsigned long long& d, unsigned long long a,
                                     unsigned long long b) {
    asm("fma.rn.f32x2 %0, %1, %2, %0;" : "+l"(d) : "l"(a), "l"(b));
}

// ---- tf32 helpers ----
__device__ __forceinline__ unsigned int f2tf32(float f) {
    unsigned int u;
    asm("cvt.rna.tf32.f32 %0, %1;" : "=r"(u) : "f"(f));
    return u;
}
__device__ __forceinline__ void mma_tf32(float& c0, float& c1, float& c2, float& c3,
                                         unsigned int a0, unsigned int a1,
                                         unsigned int a2, unsigned int a3,
                                         unsigned int b0, unsigned int b1) {
    asm("mma.sync.aligned.m16n8k8.row.col.f32.tf32.tf32.f32 "
        "{%0,%1,%2,%3}, {%4,%5,%6,%7}, {%8,%9}, {%0,%1,%2,%3};"
        : "+f"(c0), "+f"(c1), "+f"(c2), "+f"(c3)
        : "r"(a0), "r"(a1), "r"(a2), "r"(a3), "r"(b0), "r"(b1));
}

// ---------------- zeroing ----------------
__global__ void zero1_kernel() {    // S1 + deg1 (main stream, before edge1)
    int t = blockIdx.x * blockDim.x + threadIdx.x;
    int stride = gridDim.x * blockDim.x;
    float4 z = make_float4(0.f, 0.f, 0.f, 0.f);
    float4* s1 = (float4*)d_S1;
    for (int i = t; i < N0 * 25 / 4; i += stride) s1[i] = z;
    float4* dg1 = (float4*)d_deg1;
    for (int i = t; i < N0 / 4; i += stride) dg1[i] = z;
}

__global__ void zero2_kernel() {    // agg2/deg2/f1acc (side stream, joins before edge2)
    int t = blockIdx.x * blockDim.x + threadIdx.x;
    int stride = gridDim.x * blockDim.x;
    float4 z = make_float4(0.f, 0.f, 0.f, 0.f);
    float4* a2 = (float4*)d_agg2;
    for (int i = t; i < N1 * 64 / 4; i += stride) a2[i] = z;
    float4* dg2 = (float4*)d_deg2;
    for (int i = t; i < N1 / 4; i += stride) dg2[i] = z;
    float4* f1 = (float4*)d_f1acc;
    for (int i = t; i < BATCH * 512 / 4; i += stride) f1[i] = z;
}

// ---------------- layer 1 scatter: 1 thread/edge, 4 tap atomics + deg ----------------
__global__ void edge1_kernel(const float* __restrict__ x,
                             const float2* __restrict__ pseudo,
                             const int* __restrict__ ei) {
    int e = blockIdx.x * 256 + threadIdx.x;
    if (e >= E0) return;
    float2 ps = __ldg(&pseudo[e]);
    float px = ps.x * (KTAP - 1), py = ps.y * (KTAP - 1);
    float kfx = floorf(px), kfy = floorf(py);
    float fx = px - kfx, fy = py - kfy;
    int k0x = (int)kfx, k0y = (int)kfy;
    int k1x = min(k0x + 1, KTAP - 1), k1y = min(k0y + 1, KTAP - 1);
    int src = __ldg(&ei[e]);
    int dst = __ldg(&ei[E0 + e]);
    float xs = __ldg(&x[src]);
    float* Sb = d_S1 + dst * 25;
    atomicAdd(Sb + k0x * 5 + k0y, (1.f - fx) * (1.f - fy) * xs);
    atomicAdd(Sb + k0x * 5 + k1y, (1.f - fx) * fy * xs);
    atomicAdd(Sb + k1x * 5 + k0y, fx * (1.f - fy) * xs);
    atomicAdd(Sb + k1x * 5 + k1y, fx * fy * xs);
    atomicAdd(&d_deg1[dst], 1.f);
}

// ---------------- fused layer-1 node update + ELU + 2x2 maxpool ----------------
// 256 threads = 8 warps; each warp owns 4 pooled cells (8 lanes/cell).
// Warp-private coalesced staging of the 2 contiguous S1 runs per cell
// (window rows are adjacent node pairs), then compute from conflict-free LDS.
__global__ __launch_bounds__(256) void node1pool1_kernel(
        const float* __restrict__ x,
        const float* __restrict__ W1,
        const float* __restrict__ root1,
        const float* __restrict__ b1) {
    __shared__ unsigned long long sWp[25 * 16];   // W1 as f32x2 pairs
    __shared__ unsigned long long sRp[16];
    __shared__ unsigned long long sBp[16];
    __shared__ float sS[8][400];                  // [warp][cell(4) x run(2) x 50]
    __shared__ float sdeg[8][16];
    __shared__ float sx[8][16];
    int tid = threadIdx.x;
    const unsigned long long* W1q = (const unsigned long long*)W1;
    for (int i = tid; i < 400; i += 256) sWp[i] = W1q[i];
    if (tid < 16) sRp[tid] = ((const unsigned long long*)root1)[tid];
    else if (tid < 32) sBp[tid - 16] = ((const unsigned long long*)b1)[tid - 16];
    int w = tid >> 5, lane = tid & 31;
    int cell0 = blockIdx.x * 32 + w * 4;
    // stage S1 runs: 400 floats/warp, coalesced 50-float segments
    for (int idx = lane; idx < 400; idx += 32) {
        int cl = idx / 100;
        int rem = idx - cl * 100;
        int run = rem / 50;
        int off = rem - run * 50;
        int cell = cell0 + cl;
        float v = 0.f;
        if (cell < N1) {
            int b = cell / 196, r = cell % 196;
            int r2 = r / 14, c2 = r % 14;
            int nbase = b * 784 + r2 * 56 + c2 * 2 + run * 28;
            v = __ldg(&d_S1[nbase * 25 + off]);
        }
        sS[w][idx] = v;
    }
    if (lane < 16) {
        int cl = lane >> 2, nn = lane & 3;
        int cell = cell0 + cl;
        float dv = 1.f, xv = 0.f;
        if (cell < N1) {
            int b = cell / 196, r = cell % 196;
            int r2 = r / 14, c2 = r % 14;
            const int offs[4] = {0, 1, 28, 29};
            int node = b * 784 + r2 * 56 + c2 * 2 + offs[nn];
            dv = __ldg(&d_deg1[node]);
            xv = __ldg(&x[node]);
        }
        sdeg[w][lane] = dv;
        sx[w][lane] = xv;
    }
    __syncthreads();
    int cl = lane >> 3, sub = lane & 7;
    int cell = cell0 + cl;
    if (cell >= N1) return;
    float pv0 = -1e30f, pv1 = -1e30f, pv2 = -1e30f, pv3 = -1e30f;
    float r0, r1, r2f, r3, bb0, bb1, bb2, bb3;
    unpack2(sRp[sub * 2], r0, r1);
    unpack2(sRp[sub * 2 + 1], r2f, r3);
    unpack2(sBp[sub * 2], bb0, bb1);
    unpack2(sBp[sub * 2 + 1], bb2, bb3);
    #pragma unroll
    for (int nn = 0; nn < 4; nn++) {
        int run = nn >> 1, ninr = nn & 1;
        const float* Sb = &sS[w][cl * 100 + run * 50 + ninr * 25];
        unsigned long long a0 = 0ull, a1 = 0ull;
        #pragma unroll
        for (int t = 0; t < 25; t++) {
            unsigned long long sp = pack2dup(Sb[t]);
            fma2(a0, sp, sWp[t * 16 + sub * 2]);
            fma2(a1, sp, sWp[t * 16 + sub * 2 + 1]);
        }
        // deg/x index: cell-local node order is {0,1,28,29} == {run0:0,1, run1:0,1}
        int di = cl * 4 + run * 2 + ninr;
        float inv = 1.f / fmaxf(sdeg[w][di], 1.f);
        float xv = sx[w][di];
        float v0, v1, v2, v3;
        unpack2(a0, v0, v1);
        unpack2(a1, v2, v3);
        v0 = elu1(v0 * inv + xv * r0 + bb0);
        v1 = elu1(v1 * inv + xv * r1 + bb1);
        v2 = elu1(v2 * inv + xv * r2f + bb2);
        v3 = elu1(v3 * inv + xv * r3 + bb3);
        pv0 = fmaxf(pv0, v0);
        pv1 = fmaxf(pv1, v1);
        pv2 = fmaxf(pv2, v2);
        pv3 = fmaxf(pv3, v3);
    }
    ((float4*)(d_p1 + cell * 32))[sub] = make_float4(pv0, pv1, pv2, pv3);
}

// ---------------- y2 = P1[N1,32] @ W2mat[32,1600]  (tf32 MMA, bf16 store; round-14 proven) ----------------
__global__ __launch_bounds__(256) void gemm_y2_kernel(const float* __restrict__ W2) {
    __shared__ unsigned int sP[128][36];   // tf32 bits of P tile [m][k]
    __shared__ unsigned int sW[32][72];    // tf32 bits of W tap [k][n]
    int tid = threadIdx.x;
    int kk = blockIdx.x;                   // tap
    int bm = blockIdx.y * 128;
    #pragma unroll
    for (int j = 0; j < 16; j++) {
        int i = tid + j * 256;
        int r = i >> 5, c = i & 31;
        int gm = bm + r;
        sP[r][c] = f2tf32((gm < N1) ? d_p1[gm * 32 + c] : 0.f);
    }
    #pragma unroll
    for (int j = 0; j < 8; j++) {
        int i = tid + j * 256;
        int k = i >> 6, n = i & 63;
        sW[k][n] = f2tf32(W2[kk * 2048 + i]);
    }
    __syncthreads();
    int wid = tid >> 5, lane = tid & 31;
    int g = lane >> 2, t = lane & 3;
    int wm = wid * 16;
    unsigned int a[4][4];
    #pragma unroll
    for (int ks = 0; ks < 4; ks++) {
        a[ks][0] = sP[wm + g][ks * 8 + t];
        a[ks][1] = sP[wm + g + 8][ks * 8 + t];
        a[ks][2] = sP[wm + g][ks * 8 + t + 4];
        a[ks][3] = sP[wm + g + 8][ks * 8 + t + 4];
    }
    int row0 = bm + wm + g;
    int row1 = row0 + 8;
    #pragma unroll
    for (int nt = 0; nt < 8; nt++) {
        float c0 = 0.f, c1 = 0.f, c2 = 0.f, c3 = 0.f;
        #pragma unroll
        for (int ks = 0; ks < 4; ks++) {
            unsigned int b0 = sW[ks * 8 + t][nt * 8 + g];
            unsigned int b1 = sW[ks * 8 + t + 4][nt * 8 + g];
            mma_tf32(c0, c1, c2, c3, a[ks][0], a[ks][1], a[ks][2], a[ks][3], b0, b1);
        }
        int col = kk * 64 + nt * 8 + 2 * t;
        if (row0 < N1) {
            __nv_bfloat162 p = __float22bfloat162_rn(make_float2(c0, c1));
            *(__nv_bfloat162*)(d_y2 + (size_t)row0 * 1600 + col) = p;
        }
        if (row1 < N1) {
            __nv_bfloat162 p = __float22bfloat162_rn(make_float2(c2, c3));
            *(__nv_bfloat162*)(d_y2 + (size_t)row1 * 1600 + col) = p;
        }
    }
}

// ---------------- layer 2 scatter: gather 4 bf16 tap rows of y2, RED one 64-ch message ----------------
__global__ void edge2_kernel(const float2* __restrict__ pseudo,
                             const int* __restrict__ ei) {
    int sub = threadIdx.x & 15;
    int eloc = threadIdx.x >> 4;
    int e = blockIdx.x * 16 + eloc;
    if (e >= E1) return;
    float2 ps = __ldg(&pseudo[e]);
    float px = ps.x * (KTAP - 1), py = ps.y * (KTAP - 1);
    float kfx = floorf(px), kfy = floorf(py);
    float fx = px - kfx, fy = py - kfy;
    int k0x = (int)kfx, k0y = (int)kfy;
    int k1x = min(k0x + 1, KTAP - 1), k1y = min(k0y + 1, KTAP - 1);
    float w00 = (1.f - fx) * (1.f - fy);
    float w01 = (1.f - fx) * fy;
    float w10 = fx * (1.f - fy);
    float w11 = fx * fy;
    int src = __ldg(&ei[e]);
    int dst = __ldg(&ei[E1 + e]);
    const __nv_bfloat16* yb = d_y2 + (size_t)src * 1600;
    const __nv_bfloat162* t0 = (const __nv_bfloat162*)(yb + (k0x * 5 + k0y) * 64) + sub * 2;
    const __nv_bfloat162* t1 = (const __nv_bfloat162*)(yb + (k0x * 5 + k1y) * 64) + sub * 2;
    const __nv_bfloat162* t2 = (const __nv_bfloat162*)(yb + (k1x * 5 + k0y) * 64) + sub * 2;
    const __nv_bfloat162* t3 = (const __nv_bfloat162*)(yb + (k1x * 5 + k1y) * 64) + sub * 2;
    float2 v0a = __bfloat1622float2(t0[0]), v0b = __bfloat1622float2(t0[1]);
    float2 v1a = __bfloat1622float2(t1[0]), v1b = __bfloat1622float2(t1[1]);
    float2 v2a = __bfloat1622float2(t2[0]), v2b = __bfloat1622float2(t2[1]);
    float2 v3a = __bfloat1622float2(t3[0]), v3b = __bfloat1622float2(t3[1]);
    float4 m;
    m.x = w00 * v0a.x + w01 * v1a.x + w10 * v2a.x + w11 * v3a.x;
    m.y = w00 * v0a.y + w01 * v1a.y + w10 * v2a.y + w11 * v3a.y;
    m.z = w00 * v0b.x + w01 * v1b.x + w10 * v2b.x + w11 * v3b.x;
    m.w = w00 * v0b.y + w01 * v1b.y + w10 * v2b.y + w11 * v3b.y;
    red4(d_agg2 + dst * 64 + sub * 4, m);
    if (sub == 0) atomicAdd(&d_deg2[dst], 1.f);
}

// ---------------- layer 2 node: agg2/deg + p1@root2 + b2, ELU ----------------
__global__ __launch_bounds__(256) void node2_kernel(const float* __restrict__ root2,
                                                    const float* __restrict__ b2) {
    __shared__ __align__(16) float sR[32][64];
    __shared__ float sP[16][33];
    __shared__ float sdeg[16];
    int tid = threadIdx.x;
    int bn = blockIdx.x * 16;
    #pragma unroll
    for (int j = 0; j < 8; j++) {
        int i = tid + j * 256;
        ((float*)sR)[i] = root2[i];
    }
    #pragma unroll
    for (int j = 0; j < 2; j++) {
        int i = tid + j * 256;
        int r = i >> 5, c = i & 31;
        sP[r][c] = d_p1[(bn + r) * 32 + c];
    }
    if (tid < 16) sdeg[tid] = d_deg2[bn + tid];
    __syncthreads();
    int ty = tid >> 4, sub = tid & 15;
    unsigned long long a0 = 0ull, a1 = 0ull;
    #pragma unroll
    for (int i = 0; i < 32; i++) {
        unsigned long long ap = pack2dup(sP[ty][i]);
        ulonglong2 bv = *reinterpret_cast<const ulonglong2*>(&sR[i][sub * 4]);
        fma2(a0, ap, bv.x);
        fma2(a1, ap, bv.y);
    }
    int n = bn + ty;
    float inv = 1.f / fmaxf(sdeg[ty], 1.f);
    float r0, r1, r2, r3;
    unpack2(a0, r0, r1);
    unpack2(a1, r2, r3);
    float4 ag = *(const float4*)(d_agg2 + n * 64 + sub * 4);
    float4 bb = __ldg(&((const float4*)b2)[sub]);
    float4 o;
    o.x = elu1(ag.x * inv + r0 + bb.x);
    o.y = elu1(ag.y * inv + r1 + bb.y);
    o.z = elu1(ag.z * inv + r2 + bb.z);
    o.w = elu1(ag.w * inv + r3 + bb.w);
    *(float4*)(d_h2 + n * 64 + sub * 4) = o;
}

// ---------------- maxpool on [25,28,28,64] -> [25,14,14,64] (float4) ----------------
__global__ void pool2_kernel() {
    int idx = blockIdx.x * blockDim.x + threadIdx.x;
    if (idx >= NP2 * 16) return;
    int q = idx & 15;
    int m = idx >> 4;
    int c2 = m % 14, r2 = (m / 14) % 14, bb = m / 196;
    int base = (bb * 28 + r2 * 2) * 28 + c2 * 2;
    const float4* h = (const float4*)d_h2;
    float4 a0 = h[base * 16 + q];
    float4 a1 = h[(base + 1) * 16 + q];
    float4 a2 = h[(base + 28) * 16 + q];
    float4 a3 = h[(base + 29) * 16 + q];
    float4 r;
    r.x = fmaxf(fmaxf(a0.x, a1.x), fmaxf(a2.x, a3.x));
    r.y = fmaxf(fmaxf(a0.y, a1.y), fmaxf(a2.y, a3.y));
    r.z = fmaxf(fmaxf(a0.z, a1.z), fmaxf(a2.z, a3.z));
    r.w = fmaxf(fmaxf(a0.w, a1.w), fmaxf(a2.w, a3.w));
    ((float4*)d_pool2)[idx] = r;
}

// ---------------- fc1: [100,3136]@[3136,512], K split 4 ways, fp32x2, atomic combine ----------------
__global__ void fc1_kernel(const float* __restrict__ W) {
    __shared__ float sX[16][17];
    __shared__ __align__(16) float sW[16][64];
    int tid = threadIdx.x;
    int tx = tid & 15, ty = tid >> 4;
    int bn = blockIdx.x * 64;
    int bm = blockIdx.y * 16;
    int ks = blockIdx.z * 784;
    unsigned long long acc2[2] = {0ull, 0ull};
    for (int kc = 0; kc < 49; kc++) {
        int k0 = ks + kc * 16;
        {
            int gm = bm + ty;
            sX[ty][tx] = (gm < BATCH) ? d_pool2[gm * 3136 + k0 + tx] : 0.f;
        }
        #pragma unroll
        for (int j = 0; j < 4; j++) {
            int i = tid + j * 256;
            sW[i >> 6][i & 63] = W[(k0 + (i >> 6)) * 512 + bn + (i & 63)];
        }
        __syncthreads();
        #pragma unroll
        for (int k = 0; k < 16; k++) {
            unsigned long long ap = pack2dup(sX[ty][k]);
            ulonglong2 bv = *reinterpret_cast<const ulonglong2*>(&sW[k][tx * 4]);
            fma2(acc2[0], ap, bv.x);
            fma2(acc2[1], ap, bv.y);
        }
        __syncthreads();
    }
    int row = bm + ty;
    if (row < BATCH) {
        float a0, a1, a2, a3;
        unpack2(acc2[0], a0, a1);
        unpack2(acc2[1], a2, a3);
        float* p = &d_f1acc[row * 512 + bn + tx * 4];
        atomicAdd(p + 0, a0);
        atomicAdd(p + 1, a1);
        atomicAdd(p + 2, a2);
        atomicAdd(p + 3, a3);
    }
}

// ---------------- fc2 (fused fc1-bias+ELU) + ELU + log_softmax ----------------
__global__ void fc2_kernel(const float* __restrict__ f1b,
                           const float* __restrict__ W,
                           const float* __restrict__ b,
                           float* __restrict__ out) {
    __shared__ float f1row[512];
    int row = blockIdx.x;
    int tid = threadIdx.x;   // 320
    for (int k = tid; k < 512; k += 320)
        f1row[k] = elu1(d_f1acc[row * 512 + k] + __ldg(&f1b[k]));
    __syncthreads();
    int o = tid >> 5;
    int lane = tid & 31;
    float s = 0.f;
    for (int k = lane; k < 512; k += 32)
        s += f1row[k] * __ldg(&W[k * 10 + o]);
    #pragma unroll
    for (int off = 16; off; off >>= 1) s += __shfl_xor_sync(0xffffffffu, s, off);
    __shared__ float vals[10];
    if (lane == 0) vals[o] = elu1(s + b[o]);
    __syncthreads();
    if (tid == 0) {
        float mx = -1e30f;
        #pragma unroll
        for (int i = 0; i < 10; i++) mx = fmaxf(mx, vals[i]);
        float se = 0.f;
        #pragma unroll
        for (int i = 0; i < 10; i++) se += expf(vals[i] - mx);
        float lse = mx + logf(se);
        #pragma unroll
        for (int i = 0; i < 10; i++) out[row * 10 + i] = vals[i] - lse;
    }
}

extern "C" void kernel_launch(void* const* d_in, const int* in_sizes, int n_in,
                              void* d_out, int out_size) {
    const float* x        = (const float*)d_in[0];
    const float2* pseudo0 = (const float2*)d_in[1];
    const float2* pseudo1 = (const float2*)d_in[2];
    const float* W1       = (const float*)d_in[3];
    const float* root1    = (const float*)d_in[4];
    const float* b1       = (const float*)d_in[5];
    const float* W2       = (const float*)d_in[6];
    const float* root2    = (const float*)d_in[7];
    const float* b2       = (const float*)d_in[8];
    const float* fc1_w    = (const float*)d_in[9];
    const float* fc1_b    = (const float*)d_in[10];
    const float* fc2_w    = (const float*)d_in[11];
    const float* fc2_b    = (const float*)d_in[12];
    const int*   ei0      = (const int*)d_in[13];
    const int*   ei1      = (const int*)d_in[14];
    float* out = (float*)d_out;

    static cudaStream_t s2 = nullptr;
    static cudaEvent_t evFork = nullptr, evJoin = nullptr;
    if (s2 == nullptr) {
        cudaStreamCreateWithFlags(&s2, cudaStreamNonBlocking);
        cudaEventCreateWithFlags(&evFork, cudaEventDisableTiming);
        cudaEventCreateWithFlags(&evJoin, cudaEventDisableTiming);
    }

    cudaEventRecord(evFork, 0);
    cudaStreamWaitEvent(s2, evFork, 0);
    zero2_kernel<<<256, 256, 0, s2>>>();               // agg2/deg2/f1acc, overlapped
    cudaEventRecord(evJoin, s2);

    zero1_kernel<<<512, 256>>>();
    edge1_kernel<<<(E0 + 255) / 256, 256>>>(x, pseudo0, ei0);
    node1pool1_kernel<<<(N1 + 31) / 32, 256>>>(x, W1, root1, b1);
    gemm_y2_kernel<<<dim3(25, (N1 + 127) / 128), 256>>>(W2);
    cudaStreamWaitEvent(0, evJoin, 0);
    edge2_kernel<<<(E1 + 15) / 16, 256>>>(pseudo1, ei1);
    node2_kernel<<<N1 / 16, 256>>>(root2, b2);
    pool2_kernel<<<(NP2 * 16 + 255) / 256, 256>>>();
    fc1_kernel<<<dim3(8, 7, 4), 256>>>(fc1_w);
    fc2_kernel<<<BATCH, 320>>>(fc1_b, fc2_w, fc2_b, out);
}

// round 17
// speedup vs baseline: 1.0711x; 1.0711x over previous
#include <cuda_runtime.h>
#include <cuda_bf16.h>
#include <math.h>

#define KTAP 5
#define N0 78400
#define E0 627200
#define N1 19600
#define E1 156800
#define NP2 4900
#define BATCH 100

// ---------------- scratch (static device globals; no allocation) ----------------
__device__ float d_S1[N0 * 25];        // per-dst tap scalar sums (layer 1)
__device__ float d_deg1[N0];
__device__ float d_p1[N1 * 32];
__device__ __nv_bfloat16 d_y2[N1 * 1600];   // y2[n, tap(25), ch(64)] bf16 (62MB, L2-resident)
__device__ float d_agg2[N1 * 64];
__device__ float d_deg2[N1];
__device__ float d_h2[N1 * 64];
__device__ float d_pool2[NP2 * 64];    // == [100, 3136] for fc1
__device__ float d_f1acc[BATCH * 512];

__device__ __forceinline__ float elu1(float v) { return v > 0.f ? v : expm1f(v); }

__device__ __forceinline__ void red4(float* p, float4 v) {
    asm volatile("red.global.add.v4.f32 [%0], {%1,%2,%3,%4};"
                 :: "l"(p), "f"(v.x), "f"(v.y), "f"(v.z), "f"(v.w) : "memory");
}

// ---- packed fp32x2 helpers ----
__device__ __forceinline__ unsigned long long pack2dup(float a) {
    unsigned long long r;
    asm("mov.b64 %0, {%1,%1};" : "=l"(r) : "f"(a));
    return r;
}
__device__ __forceinline__ void unpack2(unsigned long long v, float& lo, float& hi) {
    asm("mov.b64 {%0,%1}, %2;" : "=f"(lo), "=f"(hi) : "l"(v));
}
__device__ __forceinline__ void fma2(unsigned long long& d, unsigned long long a,
                                     unsigned long long b) {
    asm("fma.rn.f32x2 %0, %1, %2, %0;" : "+l"(d) : "l"(a), "l"(b));
}

// ---- tf32 helpers ----
__device__ __forceinline__ unsigned int f2tf32(float f) {
    unsigned int u;
    asm("cvt.rna.tf32.f32 %0, %1;" : "=r"(u) : "f"(f));
    return u;
}
__device__ __forceinline__ void mma_tf32(float& c0, float& c1, float& c2, float& c3,
                                         unsigned int a0, unsigned int a1,
                                         unsigned int a2, unsigned int a3,
                                         unsigned int b0, unsigned int b1) {
    asm("mma.sync.aligned.m16n8k8.row.col.f32.tf32.tf32.f32 "
        "{%0,%1,%2,%3}, {%4,%5,%6,%7}, {%8,%9}, {%0,%1,%2,%3};"
        : "+f"(c0), "+f"(c1), "+f"(c2), "+f"(c3)
        : "r"(a0), "r"(a1), "r"(a2), "r"(a3), "r"(b0), "r"(b1));
}

// ---------------- zeroing ----------------
__global__ void zero1_kernel() {    // S1 + deg1 (main stream, before edge1)
    int t = blockIdx.x * blockDim.x + threadIdx.x;
    int stride = gridDim.x * blockDim.x;
    float4 z = make_float4(0.f, 0.f, 0.f, 0.f);
    float4* s1 = (float4*)d_S1;
    for (int i = t; i < N0 * 25 / 4; i += stride) s1[i] = z;
    float4* dg1 = (float4*)d_deg1;
    for (int i = t; i < N0 / 4; i += stride) dg1[i] = z;
}

__global__ void zero2_kernel() {    // agg2/deg2/f1acc (side stream, joins before edge2)
    int t = blockIdx.x * blockDim.x + threadIdx.x;
    int stride = gridDim.x * blockDim.x;
    float4 z = make_float4(0.f, 0.f, 0.f, 0.f);
    float4* a2 = (float4*)d_agg2;
    for (int i = t; i < N1 * 64 / 4; i += stride) a2[i] = z;
    float4* dg2 = (float4*)d_deg2;
    for (int i = t; i < N1 / 4; i += stride) dg2[i] = z;
    float4* f1 = (float4*)d_f1acc;
    for (int i = t; i < BATCH * 512 / 4; i += stride) f1[i] = z;
}

// ---------------- layer 1 scatter: 1 thread/edge, 4 tap atomics + deg ----------------
__global__ void edge1_kernel(const float* __restrict__ x,
                             const float2* __restrict__ pseudo,
                             const int* __restrict__ ei) {
    int e = blockIdx.x * 256 + threadIdx.x;
    if (e >= E0) return;
    float2 ps = __ldg(&pseudo[e]);
    float px = ps.x * (KTAP - 1), py = ps.y * (KTAP - 1);
    float kfx = floorf(px), kfy = floorf(py);
    float fx = px - kfx, fy = py - kfy;
    int k0x = (int)kfx, k0y = (int)kfy;
    int k1x = min(k0x + 1, KTAP - 1), k1y = min(k0y + 1, KTAP - 1);
    int src = __ldg(&ei[e]);
    int dst = __ldg(&ei[E0 + e]);
    float xs = __ldg(&x[src]);
    float* Sb = d_S1 + dst * 25;
    atomicAdd(Sb + k0x * 5 + k0y, (1.f - fx) * (1.f - fy) * xs);
    atomicAdd(Sb + k0x * 5 + k1y, (1.f - fx) * fy * xs);
    atomicAdd(Sb + k1x * 5 + k0y, fx * (1.f - fy) * xs);
    atomicAdd(Sb + k1x * 5 + k1y, fx * fy * xs);
    atomicAdd(&d_deg1[dst], 1.f);
}

// ---------------- fused layer-1 node update + ELU + 2x2 maxpool ----------------
// 8 threads per pooled cell; each thread owns a 4-channel quad (round-5 proven form)
__global__ void node1pool1_kernel(const float* __restrict__ x,
                                  const float* __restrict__ W1,
                                  const float* __restrict__ root1,
                                  const float* __restrict__ b1) {
    __shared__ unsigned long long sWp[25 * 16];   // W1 as f32x2 pairs
    __shared__ unsigned long long sRp[16];
    __shared__ unsigned long long sBp[16];
    int tid = threadIdx.x;                         // 256
    const unsigned long long* W1q = (const unsigned long long*)W1;
    for (int i = tid; i < 400; i += 256) sWp[i] = W1q[i];
    if (tid < 16) sRp[tid] = ((const unsigned long long*)root1)[tid];
    else if (tid < 32) sBp[tid - 16] = ((const unsigned long long*)b1)[tid - 16];
    __syncthreads();
    int gt = blockIdx.x * 256 + tid;
    int cell = gt >> 3;
    int sub = gt & 7;                              // channel quad index
    if (cell >= N1) return;
    int b = cell / 196, rem = cell % 196;
    int r2 = rem / 14, c2 = rem % 14;
    int base = b * 784 + r2 * 56 + c2 * 2;
    const int offs[4] = {0, 1, 28, 29};
    float pv0 = -1e30f, pv1 = -1e30f, pv2 = -1e30f, pv3 = -1e30f;
    float r0, r1, r2f, r3, bb0, bb1, bb2, bb3;
    unpack2(sRp[sub * 2], r0, r1);
    unpack2(sRp[sub * 2 + 1], r2f, r3);
    unpack2(sBp[sub * 2], bb0, bb1);
    unpack2(sBp[sub * 2 + 1], bb2, bb3);
    #pragma unroll
    for (int nn = 0; nn < 4; nn++) {
        int node = base + offs[nn];
        const float* Sb = d_S1 + node * 25;
        unsigned long long a0 = 0ull, a1 = 0ull;
        #pragma unroll
        for (int t = 0; t < 25; t++) {
            unsigned long long sp = pack2dup(__ldg(Sb + t));
            fma2(a0, sp, sWp[t * 16 + sub * 2]);
            fma2(a1, sp, sWp[t * 16 + sub * 2 + 1]);
        }
        float inv = 1.f / fmaxf(__ldg(&d_deg1[node]), 1.f);
        float xv = __ldg(&x[node]);
        float v0, v1, v2, v3;
        unpack2(a0, v0, v1);
        unpack2(a1, v2, v3);
        v0 = elu1(v0 * inv + xv * r0 + bb0);
        v1 = elu1(v1 * inv + xv * r1 + bb1);
        v2 = elu1(v2 * inv + xv * r2f + bb2);
        v3 = elu1(v3 * inv + xv * r3 + bb3);
        pv0 = fmaxf(pv0, v0);
        pv1 = fmaxf(pv1, v1);
        pv2 = fmaxf(pv2, v2);
        pv3 = fmaxf(pv3, v3);
    }
    ((float4*)(d_p1 + cell * 32))[sub] = make_float4(pv0, pv1, pv2, pv3);
}

// ---------------- y2 = P1[N1,32] @ W2mat[32,1600]  (tf32 MMA, bf16 store; round-14 proven) ----------------
__global__ __launch_bounds__(256) void gemm_y2_kernel(const float* __restrict__ W2) {
    __shared__ unsigned int sP[128][36];   // tf32 bits of P tile [m][k]
    __shared__ unsigned int sW[32][72];    // tf32 bits of W tap [k][n]
    int tid = threadIdx.x;
    int kk = blockIdx.x;                   // tap
    int bm = blockIdx.y * 128;
    #pragma unroll
    for (int j = 0; j < 16; j++) {
        int i = tid + j * 256;
        int r = i >> 5, c = i & 31;
        int gm = bm + r;
        sP[r][c] = f2tf32((gm < N1) ? d_p1[gm * 32 + c] : 0.f);
    }
    #pragma unroll
    for (int j = 0; j < 8; j++) {
        int i = tid + j * 256;
        int k = i >> 6, n = i & 63;
        sW[k][n] = f2tf32(W2[kk * 2048 + i]);
    }
    __syncthreads();
    int wid = tid >> 5, lane = tid & 31;
    int g = lane >> 2, t = lane & 3;
    int wm = wid * 16;
    unsigned int a[4][4];
    #pragma unroll
    for (int ks = 0; ks < 4; ks++) {
        a[ks][0] = sP[wm + g][ks * 8 + t];
        a[ks][1] = sP[wm + g + 8][ks * 8 + t];
        a[ks][2] = sP[wm + g][ks * 8 + t + 4];
        a[ks][3] = sP[wm + g + 8][ks * 8 + t + 4];
    }
    int row0 = bm + wm + g;
    int row1 = row0 + 8;
    #pragma unroll
    for (int nt = 0; nt < 8; nt++) {
        float c0 = 0.f, c1 = 0.f, c2 = 0.f, c3 = 0.f;
        #pragma unroll
        for (int ks = 0; ks < 4; ks++) {
            unsigned int b0 = sW[ks * 8 + t][nt * 8 + g];
            unsigned int b1 = sW[ks * 8 + t + 4][nt * 8 + g];
            mma_tf32(c0, c1, c2, c3, a[ks][0], a[ks][1], a[ks][2], a[ks][3], b0, b1);
        }
        int col = kk * 64 + nt * 8 + 2 * t;
        if (row0 < N1) {
            __nv_bfloat162 p = __float22bfloat162_rn(make_float2(c0, c1));
            *(__nv_bfloat162*)(d_y2 + (size_t)row0 * 1600 + col) = p;
        }
        if (row1 < N1) {
            __nv_bfloat162 p = __float22bfloat162_rn(make_float2(c2, c3));
            *(__nv_bfloat162*)(d_y2 + (size_t)row1 * 1600 + col) = p;
        }
    }
}

// ---------------- layer 2 scatter: gather 4 bf16 tap rows of y2, RED one 64-ch message ----------------
__global__ void edge2_kernel(const float2* __restrict__ pseudo,
                             const int* __restrict__ ei) {
    int sub = threadIdx.x & 15;
    int eloc = threadIdx.x >> 4;
    int e = blockIdx.x * 16 + eloc;
    if (e >= E1) return;
    float2 ps = __ldg(&pseudo[e]);
    float px = ps.x * (KTAP - 1), py = ps.y * (KTAP - 1);
    float kfx = floorf(px), kfy = floorf(py);
    float fx = px - kfx, fy = py - kfy;
    int k0x = (int)kfx, k0y = (int)kfy;
    int k1x = min(k0x + 1, KTAP - 1), k1y = min(k0y + 1, KTAP - 1);
    float w00 = (1.f - fx) * (1.f - fy);
    float w01 = (1.f - fx) * fy;
    float w10 = fx * (1.f - fy);
    float w11 = fx * fy;
    int src = __ldg(&ei[e]);
    int dst = __ldg(&ei[E1 + e]);
    const __nv_bfloat16* yb = d_y2 + (size_t)src * 1600;
    const __nv_bfloat162* t0 = (const __nv_bfloat162*)(yb + (k0x * 5 + k0y) * 64) + sub * 2;
    const __nv_bfloat162* t1 = (const __nv_bfloat162*)(yb + (k0x * 5 + k1y) * 64) + sub * 2;
    const __nv_bfloat162* t2 = (const __nv_bfloat162*)(yb + (k1x * 5 + k0y) * 64) + sub * 2;
    const __nv_bfloat162* t3 = (const __nv_bfloat162*)(yb + (k1x * 5 + k1y) * 64) + sub * 2;
    float2 v0a = __bfloat1622float2(t0[0]), v0b = __bfloat1622float2(t0[1]);
    float2 v1a = __bfloat1622float2(t1[0]), v1b = __bfloat1622float2(t1[1]);
    float2 v2a = __bfloat1622float2(t2[0]), v2b = __bfloat1622float2(t2[1]);
    float2 v3a = __bfloat1622float2(t3[0]), v3b = __bfloat1622float2(t3[1]);
    float4 m;
    m.x = w00 * v0a.x + w01 * v1a.x + w10 * v2a.x + w11 * v3a.x;
    m.y = w00 * v0a.y + w01 * v1a.y + w10 * v2a.y + w11 * v3a.y;
    m.z = w00 * v0b.x + w01 * v1b.x + w10 * v2b.x + w11 * v3b.x;
    m.w = w00 * v0b.y + w01 * v1b.y + w10 * v2b.y + w11 * v3b.y;
    red4(d_agg2 + dst * 64 + sub * 4, m);
    if (sub == 0) atomicAdd(&d_deg2[dst], 1.f);
}

// ---------------- layer 2 node: agg2/deg + p1@root2 + b2, ELU ----------------
__global__ __launch_bounds__(256) void node2_kernel(const float* __restrict__ root2,
                                                    const float* __restrict__ b2) {
    __shared__ __align__(16) float sR[32][64];
    __shared__ float sP[16][33];
    __shared__ float sdeg[16];
    int tid = threadIdx.x;
    int bn = blockIdx.x * 16;
    #pragma unroll
    for (int j = 0; j < 8; j++) {
        int i = tid + j * 256;
        ((float*)sR)[i] = root2[i];
    }
    #pragma unroll
    for (int j = 0; j < 2; j++) {
        int i = tid + j * 256;
        int r = i >> 5, c = i & 31;
        sP[r][c] = d_p1[(bn + r) * 32 + c];
    }
    if (tid < 16) sdeg[tid] = d_deg2[bn + tid];
    __syncthreads();
    int ty = tid >> 4, sub = tid & 15;
    unsigned long long a0 = 0ull, a1 = 0ull;
    #pragma unroll
    for (int i = 0; i < 32; i++) {
        unsigned long long ap = pack2dup(sP[ty][i]);
        ulonglong2 bv = *reinterpret_cast<const ulonglong2*>(&sR[i][sub * 4]);
        fma2(a0, ap, bv.x);
        fma2(a1, ap, bv.y);
    }
    int n = bn + ty;
    float inv = 1.f / fmaxf(sdeg[ty], 1.f);
    float r0, r1, r2, r3;
    unpack2(a0, r0, r1);
    unpack2(a1, r2, r3);
    float4 ag = *(const float4*)(d_agg2 + n * 64 + sub * 4);
    float4 bb = __ldg(&((const float4*)b2)[sub]);
    float4 o;
    o.x = elu1(ag.x * inv + r0 + bb.x);
    o.y = elu1(ag.y * inv + r1 + bb.y);
    o.z = elu1(ag.z * inv + r2 + bb.z);
    o.w = elu1(ag.w * inv + r3 + bb.w);
    *(float4*)(d_h2 + n * 64 + sub * 4) = o;
}

// ---------------- maxpool on [25,28,28,64] -> [25,14,14,64] (float4) ----------------
__global__ void pool2_kernel() {
    int idx = blockIdx.x * blockDim.x + threadIdx.x;
    if (idx >= NP2 * 16) return;
    int q = idx & 15;
    int m = idx >> 4;
    int c2 = m % 14, r2 = (m / 14) % 14, bb = m / 196;
    int base = (bb * 28 + r2 * 2) * 28 + c2 * 2;
    const float4* h = (const float4*)d_h2;
    float4 a0 = h[base * 16 + q];
    float4 a1 = h[(base + 1) * 16 + q];
    float4 a2 = h[(base + 28) * 16 + q];
    float4 a3 = h[(base + 29) * 16 + q];
    float4 r;
    r.x = fmaxf(fmaxf(a0.x, a1.x), fmaxf(a2.x, a3.x));
    r.y = fmaxf(fmaxf(a0.y, a1.y), fmaxf(a2.y, a3.y));
    r.z = fmaxf(fmaxf(a0.z, a1.z), fmaxf(a2.z, a3.z));
    r.w = fmaxf(fmaxf(a0.w, a1.w), fmaxf(a2.w, a3.w));
    ((float4*)d_pool2)[idx] = r;
}

// ---------------- fc1: [100,3136]@[3136,512], K split 4 ways, fp32x2, atomic combine ----------------
__global__ void fc1_kernel(const float* __restrict__ W) {
    __shared__ float sX[16][17];
    __shared__ __align__(16) float sW[16][64];
    int tid = threadIdx.x;
    int tx = tid & 15, ty = tid >> 4;
    int bn = blockIdx.x * 64;
    int bm = blockIdx.y * 16;
    int ks = blockIdx.z * 784;
    unsigned long long acc2[2] = {0ull, 0ull};
    for (int kc = 0; kc < 49; kc++) {
        int k0 = ks + kc * 16;
        {
            int gm = bm + ty;
            sX[ty][tx] = (gm < BATCH) ? d_pool2[gm * 3136 + k0 + tx] : 0.f;
        }
        #pragma unroll
        for (int j = 0; j < 4; j++) {
            int i = tid + j * 256;
            sW[i >> 6][i & 63] = W[(k0 + (i >> 6)) * 512 + bn + (i & 63)];
        }
        __syncthreads();
        #pragma unroll
        for (int k = 0; k < 16; k++) {
            unsigned long long ap = pack2dup(sX[ty][k]);
            ulonglong2 bv = *reinterpret_cast<const ulonglong2*>(&sW[k][tx * 4]);
            fma2(acc2[0], ap, bv.x);
            fma2(acc2[1], ap, bv.y);
        }
        __syncthreads();
    }
    int row = bm + ty;
    if (row < BATCH) {
        float a0, a1, a2, a3;
        unpack2(acc2[0], a0, a1);
        unpack2(acc2[1], a2, a3);
        float* p = &d_f1acc[row * 512 + bn + tx * 4];
        atomicAdd(p + 0, a0);
        atomicAdd(p + 1, a1);
        atomicAdd(p + 2, a2);
        atomicAdd(p + 3, a3);
    }
}

// ---------------- fc2 (fused fc1-bias+ELU) + ELU + log_softmax ----------------
__global__ void fc2_kernel(const float* __restrict__ f1b,
                           const float* __restrict__ W,
                           const float* __restrict__ b,
                           float* __restrict__ out) {
    __shared__ float f1row[512];
    int row = blockIdx.x;
    int tid = threadIdx.x;   // 320
    for (int k = tid; k < 512; k += 320)
        f1row[k] = elu1(d_f1acc[row * 512 + k] + __ldg(&f1b[k]));
    __syncthreads();
    int o = tid >> 5;
    int lane = tid & 31;
    float s = 0.f;
    for (int k = lane; k < 512; k += 32)
        s += f1row[k] * __ldg(&W[k * 10 + o]);
    #pragma unroll
    for (int off = 16; off; off >>= 1) s += __shfl_xor_sync(0xffffffffu, s, off);
    __shared__ float vals[10];
    if (lane == 0) vals[o] = elu1(s + b[o]);
    __syncthreads();
    if (tid == 0) {
        float mx = -1e30f;
        #pragma unroll
        for (int i = 0; i < 10; i++) mx = fmaxf(mx, vals[i]);
        float se = 0.f;
        #pragma unroll
        for (int i = 0; i < 10; i++) se += expf(vals[i] - mx);
        float lse = mx + logf(se);
        #pragma unroll
        for (int i = 0; i < 10; i++) out[row * 10 + i] = vals[i] - lse;
    }
}

extern "C" void kernel_launch(void* const* d_in, const int* in_sizes, int n_in,
                              void* d_out, int out_size) {
    const float* x        = (const float*)d_in[0];
    const float2* pseudo0 = (const float2*)d_in[1];
    const float2* pseudo1 = (const float2*)d_in[2];
    const float* W1       = (const float*)d_in[3];
    const float* root1    = (const float*)d_in[4];
    const float* b1       = (const float*)d_in[5];
    const float* W2       = (const float*)d_in[6];
    const float* root2    = (const float*)d_in[7];
    const float* b2       = (const float*)d_in[8];
    const float* fc1_w    = (const float*)d_in[9];
    const float* fc1_b    = (const float*)d_in[10];
    const float* fc2_w    = (const float*)d_in[11];
    const float* fc2_b    = (const float*)d_in[12];
    const int*   ei0      = (const int*)d_in[13];
    const int*   ei1      = (const int*)d_in[14];
    float* out = (float*)d_out;

    static cudaStream_t s2 = nullptr;
    static cudaEvent_t evFork = nullptr, evJoin = nullptr;
    if (s2 == nullptr) {
        cudaStreamCreateWithFlags(&s2, cudaStreamNonBlocking);
        cudaEventCreateWithFlags(&evFork, cudaEventDisableTiming);
        cudaEventCreateWithFlags(&evJoin, cudaEventDisableTiming);
    }

    cudaEventRecord(evFork, 0);
    cudaStreamWaitEvent(s2, evFork, 0);
    zero2_kernel<<<256, 256, 0, s2>>>();               // agg2/deg2/f1acc, overlapped
    cudaEventRecord(evJoin, s2);

    zero1_kernel<<<512, 256>>>();
    edge1_kernel<<<(E0 + 255) / 256, 256>>>(x, pseudo0, ei0);
    node1pool1_kernel<<<(N1 * 8 + 255) / 256, 256>>>(x, W1, root1, b1);
    gemm_y2_kernel<<<dim3(25, (N1 + 127) / 128), 256>>>(W2);
    cudaStreamWaitEvent(0, evJoin, 0);
    edge2_kernel<<<(E1 + 15) / 16, 256>>>(pseudo1, ei1);
    node2_kernel<<<N1 / 16, 256>>>(root2, b2);
    pool2_kernel<<<(NP2 * 16 + 255) / 256, 256>>>();
    fc1_kernel<<<dim3(8, 7, 4), 256>>>(fc1_w);
    fc2_kernel<<<BATCH, 320>>>(fc1_b, fc2_w, fc2_b, out);
}